// round 16
// baseline (speedup 1.0000x reference)
#include <cuda_runtime.h>
#include <cuda_bf16.h>
#include <cstdint>

#define B_    32
#define T_    1024
#define N_    1024
#define D_    256
#define WIN_  100
#define TT_   64
#define NTHREADS 512

#define KRB  528            // QK bf16 split-buffer row stride (bytes)
#define VROW 528            // V bf16 split row stride (bytes)
#define PROW 272            // P bf16 split row stride (bytes), 16B-aligned
#define PST  65             // prT f32 row stride (floats)

// phase-1 (QK) smem byte offsets
#define OFF_KH 0
#define OFF_KL (OFF_KH + 128*KRB)        //  67584
#define OFF_QH (OFF_KL + 128*KRB)        // 135168
#define OFF_QL (OFF_QH + 64*KRB)         // 168960
// phase-2 aliases (dead after QK MMA)
#define OFF_VH  0
#define OFF_VL  67584
#define OFF_PH  135168
#define OFF_PL  (OFF_PH + 64*PROW)       // 152576
#define OFF_PRT (OFF_PL + 64*PROW)       // 169984
#define SMEM_BYTES (OFF_PRT + 128*PST*4) // 203264

__device__ __forceinline__ uint32_t smem_u32(const void* p) {
    uint32_t a;
    asm("{ .reg .u64 t; cvta.to.shared.u64 t, %1; cvt.u32.u64 %0, t; }" : "=r"(a) : "l"(p));
    return a;
}
__device__ __forceinline__ void ldsm4(uint32_t* r, uint32_t addr) {
    asm volatile("ldmatrix.sync.aligned.m8n8.x4.shared.b16 {%0,%1,%2,%3}, [%4];"
                 : "=r"(r[0]), "=r"(r[1]), "=r"(r[2]), "=r"(r[3]) : "r"(addr));
}
__device__ __forceinline__ void ldsm4t(uint32_t* r, uint32_t addr) {
    asm volatile("ldmatrix.sync.aligned.m8n8.x4.trans.shared.b16 {%0,%1,%2,%3}, [%4];"
                 : "=r"(r[0]), "=r"(r[1]), "=r"(r[2]), "=r"(r[3]) : "r"(addr));
}
__device__ __forceinline__ void mma16816(float* d, const uint32_t* a, uint32_t b0, uint32_t b1) {
    asm volatile("mma.sync.aligned.m16n8k16.row.col.f32.bf16.bf16.f32 "
                 "{%0,%1,%2,%3}, {%4,%5,%6,%7}, {%8,%9}, {%0,%1,%2,%3};"
                 : "+f"(d[0]), "+f"(d[1]), "+f"(d[2]), "+f"(d[3])
                 : "r"(a[0]), "r"(a[1]), "r"(a[2]), "r"(a[3]), "r"(b0), "r"(b1));
}
__device__ __forceinline__ uint32_t cvt2bf(float hi, float lo) {
    uint32_t r;
    asm("cvt.rn.bf16x2.f32 %0, %1, %2;" : "=r"(r) : "f"(hi), "f"(lo));
    return r;
}
__device__ __forceinline__ void split8(const float* f, uint32_t* h4, uint32_t* l4) {
    #pragma unroll
    for (int i = 0; i < 4; i++) {
        uint32_t h = cvt2bf(f[2*i+1], f[2*i]);
        float h0 = __uint_as_float(h << 16);
        float h1 = __uint_as_float(h & 0xffff0000u);
        float r0 = f[2*i]   - h0;
        float r1 = f[2*i+1] - h1;
        h4[i] = h;
        l4[i] = cvt2bf(r1, r0);
    }
}

__global__ __launch_bounds__(NTHREADS, 1)
void attn_main(const float* __restrict__ Q, const float* __restrict__ K,
               const float* __restrict__ V, const int* __restrict__ prev_arr,
               float* __restrict__ out_res, float* __restrict__ out_align,
               float* __restrict__ out_max)
{
    extern __shared__ __align__(128) char sm[];
    const uint32_t smb = smem_u32(sm);
    float* prT = (float*)(sm + OFF_PRT);

    const int b    = blockIdx.y;
    const int t0   = blockIdx.x * TT_;
    const int tid  = threadIdx.x;
    const int warp = tid >> 5;
    const int lane = tid & 31;
    const int prev = prev_arr[b];

    const float* Qb = Q + ((size_t)b*T_ + t0) * D_;
    const float* Kw = K + ((size_t)b*N_ + prev) * D_;
    const float* Vw = V + ((size_t)b*N_ + prev) * D_;

    // ---- Prefetch V window into L2 ----
    #pragma unroll
    for (int it = 0; it < 2; it++) {
        int idx = tid + NTHREADS * it;
        if (idx < 800)
            asm volatile("prefetch.global.L2 [%0];" :: "l"(Vw + idx*32));
    }

    // ---- Load Q (64x256): out_res Q-half + pre-scaled split-store Qh/Ql ----
    #pragma unroll
    for (int it = 0; it < 4; it++) {
        int idx = tid + NTHREADS * it;
        int t = idx >> 5, g = idx & 31;
        const float* src = Qb + (size_t)t * D_ + 8*g;
        float4 a = *(const float4*)(src);
        float4 c = *(const float4*)(src + 4);
        float* qdst = out_res + ((size_t)b*T_ + t0 + t) * (2*D_) + 256 + 8*g;
        *(float4*)(qdst)     = a;
        *(float4*)(qdst + 4) = c;
        const float s = 0.0625f;   // fold softmax scale into Q (exact: 2^-4)
        float f[8] = {a.x*s,a.y*s,a.z*s,a.w*s,c.x*s,c.y*s,c.z*s,c.w*s};
        uint32_t h4[4], l4[4];
        split8(f, h4, l4);
        uint32_t off = (uint32_t)(t*KRB + 16*g);
        *(uint4*)(sm + OFF_QH + off) = make_uint4(h4[0],h4[1],h4[2],h4[3]);
        *(uint4*)(sm + OFF_QL + off) = make_uint4(l4[0],l4[1],l4[2],l4[3]);
    }
    // ---- Load K (rows 0..99, zero-pad to 128): split-store Kh/Kl ----
    #pragma unroll
    for (int it = 0; it < 8; it++) {
        int idx = tid + NTHREADS * it;
        int j = idx >> 5, g = idx & 31;
        float f[8] = {0,0,0,0,0,0,0,0};
        if (j < WIN_) {
            const float* src = Kw + (size_t)j * D_ + 8*g;
            float4 a = *(const float4*)(src);
            float4 c = *(const float4*)(src + 4);
            f[0]=a.x; f[1]=a.y; f[2]=a.z; f[3]=a.w; f[4]=c.x; f[5]=c.y; f[6]=c.z; f[7]=c.w;
        }
        uint32_t h4[4], l4[4];
        split8(f, h4, l4);
        uint32_t off = (uint32_t)(j*KRB + 16*g);
        *(uint4*)(sm + OFF_KH + off) = make_uint4(h4[0],h4[1],h4[2],h4[3]);
        *(uint4*)(sm + OFF_KL + off) = make_uint4(l4[0],l4[1],l4[2],l4[3]);
    }
    __syncthreads();

    // ============ QK via HMMA, operand-shared =======================================
    const int mi  = warp & 3;
    const int nj0 = (warp >> 2) * 32;
    const bool g3 = (nj0 == 96);     // group 3: only j 96..103 matter
    float dacc[4][4];
    #pragma unroll
    for (int nt = 0; nt < 4; nt++)
        #pragma unroll
        for (int i = 0; i < 4; i++) dacc[nt][i] = 0.f;

    {
        const uint32_t aOff = (uint32_t)((mi*16 + (lane & 15))*KRB + ((lane >> 4) & 1)*16);
        const int nB = nj0 + ((lane >> 4) & 1)*8 + (lane & 7);
        const uint32_t bOff = (uint32_t)(nB*KRB + ((lane >> 3) & 1)*16);
        const uint32_t aQh = smb + OFF_QH + aOff;
        const uint32_t aQl = smb + OFF_QL + aOff;
        const uint32_t bKh0 = smb + OFF_KH + bOff;
        const uint32_t bKl0 = smb + OFF_KL + bOff;

        if (!g3) {
            #pragma unroll 2
            for (int ks = 0; ks < 16; ks++) {
                uint32_t ah[4], al[4], bh0[4], bh1[4], bl0[4], bl1[4];
                ldsm4(ah,  aQh + ks*32);
                ldsm4(al,  aQl + ks*32);
                ldsm4(bh0, bKh0 + ks*32);
                ldsm4(bh1, bKh0 + 16*KRB + ks*32);
                ldsm4(bl0, bKl0 + ks*32);
                ldsm4(bl1, bKl0 + 16*KRB + ks*32);
                mma16816(dacc[0], ah, bh0[0], bh0[1]);
                mma16816(dacc[1], ah, bh0[2], bh0[3]);
                mma16816(dacc[2], ah, bh1[0], bh1[1]);
                mma16816(dacc[3], ah, bh1[2], bh1[3]);
                mma16816(dacc[0], ah, bl0[0], bl0[1]);
                mma16816(dacc[1], ah, bl0[2], bl0[3]);
                mma16816(dacc[2], ah, bl1[0], bl1[1]);
                mma16816(dacc[3], ah, bl1[2], bl1[3]);
                mma16816(dacc[0], al, bh0[0], bh0[1]);
                mma16816(dacc[1], al, bh0[2], bh0[3]);
                mma16816(dacc[2], al, bh1[0], bh1[1]);
                mma16816(dacc[3], al, bh1[2], bh1[3]);
            }
        } else {
            // group 3: single n8 tile (j 96..103); rest of its j-range is past the window
            #pragma unroll 2
            for (int ks = 0; ks < 16; ks++) {
                uint32_t ah[4], al[4], bh0[4], bl0[4];
                ldsm4(ah,  aQh + ks*32);
                ldsm4(al,  aQl + ks*32);
                ldsm4(bh0, bKh0 + ks*32);
                ldsm4(bl0, bKl0 + ks*32);
                mma16816(dacc[0], ah, bh0[0], bh0[1]);
                mma16816(dacc[0], ah, bl0[0], bl0[1]);
                mma16816(dacc[0], al, bh0[0], bh0[1]);
            }
        }
    }
    __syncthreads();   // QK smem reads complete -> aliasing legal

    // ---- Store scores transposed into prT[j][t] (already scaled via Q) ----
    {
        int tb = mi*16 + (lane >> 2);
        int jb = nj0 + (lane & 3)*2;
        const int ntl = g3 ? 1 : 4;
        #pragma unroll
        for (int nt = 0; nt < 4; nt++) {
            if (nt >= ntl) break;
            int j = jb + nt*8;
            prT[(j  )*PST + tb    ] = dacc[nt][0];
            prT[(j+1)*PST + tb    ] = dacc[nt][1];
            prT[(j  )*PST + tb + 8] = dacc[nt][2];
            prT[(j+1)*PST + tb + 8] = dacc[nt][3];
        }
    }
    __syncthreads();   // scores visible

    // ============ Phase 3 (warp-specialized) ========================================
    if (warp < 8) {
        // warps 0..7: softmax + argmax + P-split, rows t in [8w, 8w+8)
        const int trow = warp * 8;
        const bool in1 = (lane < 18);
        #pragma unroll
        for (int tt = 0; tt < 8; tt++) {
            int t = trow + tt;
            float v0 = prT[(2*lane  )*PST + t];
            float v1 = prT[(2*lane+1)*PST + t];
            float v2 = prT[(64+2*lane)*PST + t];
            float v3 = prT[(65+2*lane)*PST + t];

            float mx = fmaxf(v0, v1);
            if (in1) mx = fmaxf(mx, fmaxf(v2, v3));
            #pragma unroll
            for (int off = 16; off; off >>= 1)
                mx = fmaxf(mx, __shfl_xor_sync(0xffffffffu, mx, off));

            float e0 = __expf(v0 - mx);
            float e1 = __expf(v1 - mx);
            float e2 = in1 ? __expf(v2 - mx) : 0.f;
            float e3 = in1 ? __expf(v3 - mx) : 0.f;
            float s = (e0 + e1) + (e2 + e3);
            #pragma unroll
            for (int off = 16; off; off >>= 1)
                s += __shfl_xor_sync(0xffffffffu, s, off);
            float inv = 1.f / s;

            float p0 = e0*inv, p1 = e1*inv, p2 = e2*inv, p3 = e3*inv;

            float bm = p0; int bi = 2*lane;
            if (p1 > bm) { bm = p1; bi = 2*lane+1; }
            if (p2 > bm) { bm = p2; bi = 64+2*lane; }
            if (p3 > bm) { bm = p3; bi = 65+2*lane; }
            #pragma unroll
            for (int off = 16; off; off >>= 1) {
                float om = __shfl_xor_sync(0xffffffffu, bm, off);
                int   oi = __shfl_xor_sync(0xffffffffu, bi, off);
                if (om > bm || (om == bm && oi < bi)) { bm = om; bi = oi; }
            }
            if (lane == 0)
                out_max[(size_t)b*T_ + t0 + t] = (float)(prev + bi);

            prT[(2*lane  )*PST + t] = p0;
            prT[(2*lane+1)*PST + t] = p1;
            prT[(64+2*lane)*PST + t] = p2;
            prT[(65+2*lane)*PST + t] = p3;

            uint32_t h01 = cvt2bf(p1, p0);
            float rh0 = p0 - __uint_as_float(h01 << 16);
            float rh1 = p1 - __uint_as_float(h01 & 0xffff0000u);
            uint32_t l01 = cvt2bf(rh1, rh0);
            uint32_t h23 = cvt2bf(p3, p2);
            float rh2 = p2 - __uint_as_float(h23 << 16);
            float rh3 = p3 - __uint_as_float(h23 & 0xffff0000u);
            uint32_t l23 = cvt2bf(rh3, rh2);
            *(uint32_t*)(sm + OFF_PH + t*PROW + 4*lane)       = h01;
            *(uint32_t*)(sm + OFF_PL + t*PROW + 4*lane)       = l01;
            *(uint32_t*)(sm + OFF_PH + t*PROW + 128 + 4*lane) = h23;
            *(uint32_t*)(sm + OFF_PL + t*PROW + 128 + 4*lane) = l23;
        }
    } else {
        // warps 8..15: V load+split only (zero-fill moved to kernel tail)
        const int ltid = tid - 256;
        #pragma unroll
        for (int it = 0; it < 16; it++) {
            int idx = ltid + 256 * it;
            int j = idx >> 5, g = idx & 31;
            float f[8] = {0,0,0,0,0,0,0,0};
            if (j < WIN_) {
                const float* src = Vw + (size_t)j * D_ + 8*g;
                float4 a = *(const float4*)(src);
                float4 c = *(const float4*)(src + 4);
                f[0]=a.x; f[1]=a.y; f[2]=a.z; f[3]=a.w; f[4]=c.x; f[5]=c.y; f[6]=c.z; f[7]=c.w;
            }
            uint32_t h4[4], l4[4];
            split8(f, h4, l4);
            uint32_t off = (uint32_t)(j*VROW + 16*g);
            *(uint4*)(sm + OFF_VH + off) = make_uint4(h4[0],h4[1],h4[2],h4[3]);
            *(uint4*)(sm + OFF_VL + off) = make_uint4(l4[0],l4[1],l4[2],l4[3]);
        }
    }
    __syncthreads();

    // ============ PV via HMMA, operand-shared, ks trimmed to 7 (k<=112) ============
    {
        const int d0g = (warp >> 2) * 64;
        float oacc[8][4];
        #pragma unroll
        for (int nt = 0; nt < 8; nt++)
            #pragma unroll
            for (int i = 0; i < 4; i++) oacc[nt][i] = 0.f;

        const uint32_t aPOff = (uint32_t)((mi*16 + (lane & 15))*PROW + ((lane >> 4) & 1)*16);
        const uint32_t bVOff = (uint32_t)((lane & 15)*VROW + d0g*2 + ((lane >> 4) & 1)*16);
        const uint32_t aPH = smb + OFF_PH + aPOff;
        const uint32_t aPL = smb + OFF_PL + aPOff;
        const uint32_t bVH = smb + OFF_VH + bVOff;
        const uint32_t bVL = smb + OFF_VL + bVOff;

        #pragma unroll 1
        for (int ks = 0; ks < 7; ks++) {     // k rows 0..111 cover window (>=100 are exact zeros)
            uint32_t ph[4], pl[4], vh[4][4], vl[4][4];
            ldsm4(ph, aPH + ks*32);
            ldsm4(pl, aPL + ks*32);
            uint32_t rowH = bVH + ks*(16*VROW);
            uint32_t rowL = bVL + ks*(16*VROW);
            #pragma unroll
            for (int np = 0; np < 4; np++) {
                ldsm4t(vh[np], rowH + np*32);
                ldsm4t(vl[np], rowL + np*32);
            }
            #pragma unroll
            for (int np = 0; np < 4; np++) {
                mma16816(oacc[2*np],   ph, vh[np][0], vh[np][1]);
                mma16816(oacc[2*np+1], ph, vh[np][2], vh[np][3]);
                mma16816(oacc[2*np],   pl, vh[np][0], vh[np][1]);
                mma16816(oacc[2*np+1], pl, vh[np][2], vh[np][3]);
                mma16816(oacc[2*np],   ph, vl[np][0], vl[np][1]);
                mma16816(oacc[2*np+1], ph, vl[np][2], vl[np][3]);
            }
        }
        int tr = mi*16 + (lane >> 2);
        int dc = (lane & 3)*2;
        #pragma unroll
        for (int nt = 0; nt < 8; nt++) {
            int d = d0g + nt*8 + dc;
            float* o0 = out_res + ((size_t)b*T_ + t0 + tr    )*(2*D_) + d;
            float* o1 = out_res + ((size_t)b*T_ + t0 + tr + 8)*(2*D_) + d;
            *(float2*)o0 = make_float2(oacc[nt][0], oacc[nt][1]);
            *(float2*)o1 = make_float2(oacc[nt][2], oacc[nt][3]);
        }
    }

    // ============ Tail: alignments band + zero-fill (all 16 warps, no barrier) ======
    #pragma unroll 1
    for (int j = warp; j < WIN_; j += 16) {
        float* ar = out_align + ((size_t)b*N_ + prev + j)*T_ + t0;
        ar[lane]      = prT[j*PST + lane];
        ar[32 + lane] = prT[j*PST + 32 + lane];
    }
    #pragma unroll 1
    for (int r = warp; r < N_; r += 16) {
        if (r >= prev && r < prev + WIN_) continue;
        float* ar = out_align + ((size_t)b*N_ + r)*T_ + t0;
        *(float2*)(ar + lane*2) = make_float2(0.f, 0.f);
    }
}

extern "C" void kernel_launch(void* const* d_in, const int* in_sizes, int n_in,
                              void* d_out, int out_size)
{
    const float* Q    = (const float*)d_in[0];
    const float* K    = (const float*)d_in[1];
    const float* V    = (const float*)d_in[2];
    const int*   prev = (const int*)d_in[3];

    float* out       = (float*)d_out;
    float* out_res   = out;                                   // B*T*2D
    float* out_align = out + (size_t)B_*T_*2*D_;              // B*N*T
    float* out_max   = out_align + (size_t)B_*N_*T_;          // B*T

    cudaFuncSetAttribute(attn_main, cudaFuncAttributeMaxDynamicSharedMemorySize, SMEM_BYTES);
    dim3 grid(T_/TT_, B_);
    attn_main<<<grid, NTHREADS, SMEM_BYTES>>>(Q, K, V, prev, out_res, out_align, out_max);
}

// round 17
// speedup vs baseline: 1.1176x; 1.1176x over previous
#include <cuda_runtime.h>
#include <cuda_bf16.h>
#include <cstdint>

#define B_    32
#define T_    1024
#define N_    1024
#define D_    256
#define WIN_  100
#define TT_   64
#define NTHREADS 512

#define KRB  528            // QK bf16 split-buffer row stride (bytes)
#define VROW 528            // V bf16 split row stride (bytes)
#define PROW 272            // P bf16 split row stride (bytes), 16B-aligned
#define PST  65             // prT f32 row stride (floats)

// phase-1 (QK) smem byte offsets
#define OFF_KH 0
#define OFF_KL (OFF_KH + 128*KRB)        //  67584
#define OFF_QH (OFF_KL + 128*KRB)        // 135168
#define OFF_QL (OFF_QH + 64*KRB)         // 168960
// phase-2 aliases (dead after QK MMA)
#define OFF_VH  0
#define OFF_VL  67584
#define OFF_PH  135168
#define OFF_PL  (OFF_PH + 64*PROW)       // 152576
#define OFF_PRT (OFF_PL + 64*PROW)       // 169984
#define SMEM_BYTES (OFF_PRT + 128*PST*4) // 203264

__device__ __forceinline__ uint32_t smem_u32(const void* p) {
    uint32_t a;
    asm("{ .reg .u64 t; cvta.to.shared.u64 t, %1; cvt.u32.u64 %0, t; }" : "=r"(a) : "l"(p));
    return a;
}
__device__ __forceinline__ void ldsm4(uint32_t* r, uint32_t addr) {
    asm volatile("ldmatrix.sync.aligned.m8n8.x4.shared.b16 {%0,%1,%2,%3}, [%4];"
                 : "=r"(r[0]), "=r"(r[1]), "=r"(r[2]), "=r"(r[3]) : "r"(addr));
}
__device__ __forceinline__ void ldsm4t(uint32_t* r, uint32_t addr) {
    asm volatile("ldmatrix.sync.aligned.m8n8.x4.trans.shared.b16 {%0,%1,%2,%3}, [%4];"
                 : "=r"(r[0]), "=r"(r[1]), "=r"(r[2]), "=r"(r[3]) : "r"(addr));
}
__device__ __forceinline__ void mma16816(float* d, const uint32_t* a, uint32_t b0, uint32_t b1) {
    asm volatile("mma.sync.aligned.m16n8k16.row.col.f32.bf16.bf16.f32 "
                 "{%0,%1,%2,%3}, {%4,%5,%6,%7}, {%8,%9}, {%0,%1,%2,%3};"
                 : "+f"(d[0]), "+f"(d[1]), "+f"(d[2]), "+f"(d[3])
                 : "r"(a[0]), "r"(a[1]), "r"(a[2]), "r"(a[3]), "r"(b0), "r"(b1));
}
__device__ __forceinline__ uint32_t cvt2bf(float hi, float lo) {
    uint32_t r;
    asm("cvt.rn.bf16x2.f32 %0, %1, %2;" : "=r"(r) : "f"(hi), "f"(lo));
    return r;
}
__device__ __forceinline__ void split8(const float* f, uint32_t* h4, uint32_t* l4) {
    #pragma unroll
    for (int i = 0; i < 4; i++) {
        uint32_t h = cvt2bf(f[2*i+1], f[2*i]);
        float h0 = __uint_as_float(h << 16);
        float h1 = __uint_as_float(h & 0xffff0000u);
        float r0 = f[2*i]   - h0;
        float r1 = f[2*i+1] - h1;
        h4[i] = h;
        l4[i] = cvt2bf(r1, r0);
    }
}

__global__ __launch_bounds__(NTHREADS, 1)
void attn_main(const float* __restrict__ Q, const float* __restrict__ K,
               const float* __restrict__ V, const int* __restrict__ prev_arr,
               float* __restrict__ out_res, float* __restrict__ out_align,
               float* __restrict__ out_max)
{
    extern __shared__ __align__(128) char sm[];
    const uint32_t smb = smem_u32(sm);
    float* prT = (float*)(sm + OFF_PRT);

    const int b    = blockIdx.y;
    const int t0   = blockIdx.x * TT_;
    const int tid  = threadIdx.x;
    const int warp = tid >> 5;
    const int lane = tid & 31;
    const int prev = prev_arr[b];

    const float* Qb = Q + ((size_t)b*T_ + t0) * D_;
    const float* Kw = K + ((size_t)b*N_ + prev) * D_;
    const float* Vw = V + ((size_t)b*N_ + prev) * D_;

    // ---- Prefetch V window into L2 ----
    #pragma unroll
    for (int it = 0; it < 2; it++) {
        int idx = tid + NTHREADS * it;
        if (idx < 800)
            asm volatile("prefetch.global.L2 [%0];" :: "l"(Vw + idx*32));
    }

    // ---- Load Q (64x256): out_res Q-half + pre-scaled split-store Qh/Ql ----
    #pragma unroll
    for (int it = 0; it < 4; it++) {
        int idx = tid + NTHREADS * it;
        int t = idx >> 5, g = idx & 31;
        const float* src = Qb + (size_t)t * D_ + 8*g;
        float4 a = *(const float4*)(src);
        float4 c = *(const float4*)(src + 4);
        float* qdst = out_res + ((size_t)b*T_ + t0 + t) * (2*D_) + 256 + 8*g;
        *(float4*)(qdst)     = a;
        *(float4*)(qdst + 4) = c;
        const float s = 0.0625f;   // fold softmax scale into Q (exact: 2^-4)
        float f[8] = {a.x*s,a.y*s,a.z*s,a.w*s,c.x*s,c.y*s,c.z*s,c.w*s};
        uint32_t h4[4], l4[4];
        split8(f, h4, l4);
        uint32_t off = (uint32_t)(t*KRB + 16*g);
        *(uint4*)(sm + OFF_QH + off) = make_uint4(h4[0],h4[1],h4[2],h4[3]);
        *(uint4*)(sm + OFF_QL + off) = make_uint4(l4[0],l4[1],l4[2],l4[3]);
    }
    // ---- Load K (rows 0..99, zero-pad to 128): split-store Kh/Kl ----
    #pragma unroll
    for (int it = 0; it < 8; it++) {
        int idx = tid + NTHREADS * it;
        int j = idx >> 5, g = idx & 31;
        float f[8] = {0,0,0,0,0,0,0,0};
        if (j < WIN_) {
            const float* src = Kw + (size_t)j * D_ + 8*g;
            float4 a = *(const float4*)(src);
            float4 c = *(const float4*)(src + 4);
            f[0]=a.x; f[1]=a.y; f[2]=a.z; f[3]=a.w; f[4]=c.x; f[5]=c.y; f[6]=c.z; f[7]=c.w;
        }
        uint32_t h4[4], l4[4];
        split8(f, h4, l4);
        uint32_t off = (uint32_t)(j*KRB + 16*g);
        *(uint4*)(sm + OFF_KH + off) = make_uint4(h4[0],h4[1],h4[2],h4[3]);
        *(uint4*)(sm + OFF_KL + off) = make_uint4(l4[0],l4[1],l4[2],l4[3]);
    }
    __syncthreads();

    // ============ QK via HMMA, operand-shared: 6 ldsm + 12 mma per ks ===============
    const int mi  = warp & 3;
    const int nj0 = (warp >> 2) * 32;
    float dacc[4][4];
    #pragma unroll
    for (int nt = 0; nt < 4; nt++)
        #pragma unroll
        for (int i = 0; i < 4; i++) dacc[nt][i] = 0.f;

    {
        const uint32_t aOff = (uint32_t)((mi*16 + (lane & 15))*KRB + ((lane >> 4) & 1)*16);
        const int nB = nj0 + ((lane >> 4) & 1)*8 + (lane & 7);
        const uint32_t bOff = (uint32_t)(nB*KRB + ((lane >> 3) & 1)*16);
        const uint32_t aQh = smb + OFF_QH + aOff;
        const uint32_t aQl = smb + OFF_QL + aOff;
        const uint32_t bKh0 = smb + OFF_KH + bOff;
        const uint32_t bKl0 = smb + OFF_KL + bOff;

        #pragma unroll 2
        for (int ks = 0; ks < 16; ks++) {
            uint32_t ah[4], al[4], bh0[4], bh1[4], bl0[4], bl1[4];
            ldsm4(ah,  aQh + ks*32);
            ldsm4(al,  aQl + ks*32);
            ldsm4(bh0, bKh0 + ks*32);
            ldsm4(bh1, bKh0 + 16*KRB + ks*32);
            ldsm4(bl0, bKl0 + ks*32);
            ldsm4(bl1, bKl0 + 16*KRB + ks*32);
            // term Qh*Kh
            mma16816(dacc[0], ah, bh0[0], bh0[1]);
            mma16816(dacc[1], ah, bh0[2], bh0[3]);
            mma16816(dacc[2], ah, bh1[0], bh1[1]);
            mma16816(dacc[3], ah, bh1[2], bh1[3]);
            // term Qh*Kl
            mma16816(dacc[0], ah, bl0[0], bl0[1]);
            mma16816(dacc[1], ah, bl0[2], bl0[3]);
            mma16816(dacc[2], ah, bl1[0], bl1[1]);
            mma16816(dacc[3], ah, bl1[2], bl1[3]);
            // term Ql*Kh
            mma16816(dacc[0], al, bh0[0], bh0[1]);
            mma16816(dacc[1], al, bh0[2], bh0[3]);
            mma16816(dacc[2], al, bh1[0], bh1[1]);
            mma16816(dacc[3], al, bh1[2], bh1[3]);
        }
    }
    __syncthreads();   // QK smem reads complete -> aliasing legal

    // ---- Store scores transposed into prT[j][t] (already scaled via Q) ----
    {
        int tb = mi*16 + (lane >> 2);
        int jb = nj0 + (lane & 3)*2;
        #pragma unroll
        for (int nt = 0; nt < 4; nt++) {
            int j = jb + nt*8;
            prT[(j  )*PST + tb    ] = dacc[nt][0];
            prT[(j+1)*PST + tb    ] = dacc[nt][1];
            prT[(j  )*PST + tb + 8] = dacc[nt][2];
            prT[(j+1)*PST + tb + 8] = dacc[nt][3];
        }
    }
    __syncthreads();   // scores visible

    // ============ Phase 3 (warp-specialized) ========================================
    if (warp < 8) {
        // warps 0..7: softmax + argmax + P-split, rows t in [8w, 8w+8)
        const int trow = warp * 8;
        const bool in1 = (lane < 18);
        #pragma unroll
        for (int tt = 0; tt < 8; tt++) {
            int t = trow + tt;
            float v0 = prT[(2*lane  )*PST + t];
            float v1 = prT[(2*lane+1)*PST + t];
            float v2 = prT[(64+2*lane)*PST + t];
            float v3 = prT[(65+2*lane)*PST + t];

            float mx = fmaxf(v0, v1);
            if (in1) mx = fmaxf(mx, fmaxf(v2, v3));
            #pragma unroll
            for (int off = 16; off; off >>= 1)
                mx = fmaxf(mx, __shfl_xor_sync(0xffffffffu, mx, off));

            float e0 = __expf(v0 - mx);
            float e1 = __expf(v1 - mx);
            float e2 = in1 ? __expf(v2 - mx) : 0.f;
            float e3 = in1 ? __expf(v3 - mx) : 0.f;
            float s = (e0 + e1) + (e2 + e3);
            #pragma unroll
            for (int off = 16; off; off >>= 1)
                s += __shfl_xor_sync(0xffffffffu, s, off);
            float inv = 1.f / s;

            float p0 = e0*inv, p1 = e1*inv, p2 = e2*inv, p3 = e3*inv;

            float bm = p0; int bi = 2*lane;
            if (p1 > bm) { bm = p1; bi = 2*lane+1; }
            if (p2 > bm) { bm = p2; bi = 64+2*lane; }
            if (p3 > bm) { bm = p3; bi = 65+2*lane; }
            #pragma unroll
            for (int off = 16; off; off >>= 1) {
                float om = __shfl_xor_sync(0xffffffffu, bm, off);
                int   oi = __shfl_xor_sync(0xffffffffu, bi, off);
                if (om > bm || (om == bm && oi < bi)) { bm = om; bi = oi; }
            }
            if (lane == 0)
                out_max[(size_t)b*T_ + t0 + t] = (float)(prev + bi);

            prT[(2*lane  )*PST + t] = p0;
            prT[(2*lane+1)*PST + t] = p1;
            prT[(64+2*lane)*PST + t] = p2;
            prT[(65+2*lane)*PST + t] = p3;

            uint32_t h01 = cvt2bf(p1, p0);
            float rh0 = p0 - __uint_as_float(h01 << 16);
            float rh1 = p1 - __uint_as_float(h01 & 0xffff0000u);
            uint32_t l01 = cvt2bf(rh1, rh0);
            uint32_t h23 = cvt2bf(p3, p2);
            float rh2 = p2 - __uint_as_float(h23 << 16);
            float rh3 = p3 - __uint_as_float(h23 & 0xffff0000u);
            uint32_t l23 = cvt2bf(rh3, rh2);
            *(uint32_t*)(sm + OFF_PH + t*PROW + 4*lane)       = h01;
            *(uint32_t*)(sm + OFF_PL + t*PROW + 4*lane)       = l01;
            *(uint32_t*)(sm + OFF_PH + t*PROW + 128 + 4*lane) = h23;
            *(uint32_t*)(sm + OFF_PL + t*PROW + 128 + 4*lane) = l23;
        }
    } else {
        // warps 8..15: V load+split (over KH/KL) + alignments zero-fill
        const int ltid = tid - 256;
        #pragma unroll
        for (int it = 0; it < 16; it++) {
            int idx = ltid + 256 * it;
            int j = idx >> 5, g = idx & 31;
            float f[8] = {0,0,0,0,0,0,0,0};
            if (j < WIN_) {
                const float* src = Vw + (size_t)j * D_ + 8*g;
                float4 a = *(const float4*)(src);
                float4 c = *(const float4*)(src + 4);
                f[0]=a.x; f[1]=a.y; f[2]=a.z; f[3]=a.w; f[4]=c.x; f[5]=c.y; f[6]=c.z; f[7]=c.w;
            }
            uint32_t h4[4], l4[4];
            split8(f, h4, l4);
            uint32_t off = (uint32_t)(j*VROW + 16*g);
            *(uint4*)(sm + OFF_VH + off) = make_uint4(h4[0],h4[1],h4[2],h4[3]);
            *(uint4*)(sm + OFF_VL + off) = make_uint4(l4[0],l4[1],l4[2],l4[3]);
        }
        #pragma unroll 1
        for (int r = warp - 8; r < N_; r += 8) {
            if (r >= prev && r < prev + WIN_) continue;
            float* ar = out_align + ((size_t)b*N_ + r)*T_ + t0;
            *(float2*)(ar + lane*2) = make_float2(0.f, 0.f);
        }
    }
    __syncthreads();

    // ---- Alignments band rows (coalesced) ----
    #pragma unroll 1
    for (int j = warp; j < WIN_; j += 16) {
        float* ar = out_align + ((size_t)b*N_ + prev + j)*T_ + t0;
        ar[lane]      = prT[j*PST + lane];
        ar[32 + lane] = prT[j*PST + 32 + lane];
    }

    // ============ PV via HMMA, operand-shared, ks trimmed to 7 (k<=112) ============
    {
        const int d0g = (warp >> 2) * 64;
        float oacc[8][4];
        #pragma unroll
        for (int nt = 0; nt < 8; nt++)
            #pragma unroll
            for (int i = 0; i < 4; i++) oacc[nt][i] = 0.f;

        const uint32_t aPOff = (uint32_t)((mi*16 + (lane & 15))*PROW + ((lane >> 4) & 1)*16);
        const uint32_t bVOff = (uint32_t)((lane & 15)*VROW + d0g*2 + ((lane >> 4) & 1)*16);
        const uint32_t aPH = smb + OFF_PH + aPOff;
        const uint32_t aPL = smb + OFF_PL + aPOff;
        const uint32_t bVH = smb + OFF_VH + bVOff;
        const uint32_t bVL = smb + OFF_VL + bVOff;

        #pragma unroll 1
        for (int ks = 0; ks < 7; ks++) {   // k rows 0..111; rows >=100 exact zeros -> bit-identical
            uint32_t ph[4], pl[4], vh[4][4], vl[4][4];
            ldsm4(ph, aPH + ks*32);
            ldsm4(pl, aPL + ks*32);
            uint32_t rowH = bVH + ks*(16*VROW);
            uint32_t rowL = bVL + ks*(16*VROW);
            #pragma unroll
            for (int np = 0; np < 4; np++) {
                ldsm4t(vh[np], rowH + np*32);
                ldsm4t(vl[np], rowL + np*32);
            }
            #pragma unroll
            for (int np = 0; np < 4; np++) {
                mma16816(oacc[2*np],   ph, vh[np][0], vh[np][1]);
                mma16816(oacc[2*np+1], ph, vh[np][2], vh[np][3]);
                mma16816(oacc[2*np],   pl, vh[np][0], vh[np][1]);
                mma16816(oacc[2*np+1], pl, vh[np][2], vh[np][3]);
                mma16816(oacc[2*np],   ph, vl[np][0], vl[np][1]);
                mma16816(oacc[2*np+1], ph, vl[np][2], vl[np][3]);
            }
        }
        int tr = mi*16 + (lane >> 2);
        int dc = (lane & 3)*2;
        #pragma unroll
        for (int nt = 0; nt < 8; nt++) {
            int d = d0g + nt*8 + dc;
            float* o0 = out_res + ((size_t)b*T_ + t0 + tr    )*(2*D_) + d;
            float* o1 = out_res + ((size_t)b*T_ + t0 + tr + 8)*(2*D_) + d;
            *(float2*)o0 = make_float2(oacc[nt][0], oacc[nt][1]);
            *(float2*)o1 = make_float2(oacc[nt][2], oacc[nt][3]);
        }
    }
}

extern "C" void kernel_launch(void* const* d_in, const int* in_sizes, int n_in,
                              void* d_out, int out_size)
{
    const float* Q    = (const float*)d_in[0];
    const float* K    = (const float*)d_in[1];
    const float* V    = (const float*)d_in[2];
    const int*   prev = (const int*)d_in[3];

    float* out       = (float*)d_out;
    float* out_res   = out;                                   // B*T*2D
    float* out_align = out + (size_t)B_*T_*2*D_;              // B*N*T
    float* out_max   = out_align + (size_t)B_*N_*T_;          // B*T

    cudaFuncSetAttribute(attn_main, cudaFuncAttributeMaxDynamicSharedMemorySize, SMEM_BYTES);
    dim3 grid(T_/TT_, B_);
    attn_main<<<grid, NTHREADS, SMEM_BYTES>>>(Q, K, V, prev, out_res, out_align, out_max);
}